// round 7
// baseline (speedup 1.0000x reference)
#include <cuda_runtime.h>
#include <cuda_fp16.h>
#include <cstdint>

#define DIMX 768
#define DEMBX 512
#define NSRC 8192
#define NLTN 64
#define NSLAB 8
#define NCTX 8256                 // per-slab context rows (src + ltn)
#define MROWS (NSLAB * NCTX)      // 66048
#define NSPLIT 3
#define TILES_PER_SPLIT 43        // 129 tiles / 3

// ---------------- scratch (static device globals: allowed) ----------------
__device__ __half g_ctx[(size_t)MROWS * DIMX];        // normalized context, fp16
__device__ __half g_ltnc[(size_t)NSLAB * NLTN * DIMX];// compact normalized ltn
__device__ __half g_wq[DIMX * DEMBX];
__device__ __half g_wkv[DIMX * 2 * DEMBX];
__device__ __half g_wo[DEMBX * DIMX];
__device__ __half g_q[NSLAB * NLTN * DEMBX];
__device__ __half g_kv[(size_t)MROWS * 2 * DEMBX];    // K | V
__device__ __half g_att[NSLAB * NLTN * DEMBX];
__device__ float g_po[NSPLIT * 64 * 64 * 64];
__device__ float g_pm[NSPLIT * 64 * 64];
__device__ float g_pl[NSPLIT * 64 * 64];

// ---------------- helpers ----------------
__device__ __forceinline__ uint32_t smem_u32(const void* p) {
    return (uint32_t)__cvta_generic_to_shared(p);
}
__device__ __forceinline__ void cp16(uint32_t s, const void* g) {
    asm volatile("cp.async.cg.shared.global [%0], [%1], 16;\n" :: "r"(s), "l"(g));
}
#define CP_COMMIT() asm volatile("cp.async.commit_group;\n")
#define CP_WAIT0()  asm volatile("cp.async.wait_group 0;\n")
#define CP_WAIT1()  asm volatile("cp.async.wait_group 1;\n")
#define CP_WAIT2()  asm volatile("cp.async.wait_group 2;\n")

__device__ __forceinline__ void ldm_x4(uint32_t r[4], uint32_t addr) {
    asm volatile("ldmatrix.sync.aligned.m8n8.x4.shared.b16 {%0,%1,%2,%3}, [%4];\n"
        : "=r"(r[0]), "=r"(r[1]), "=r"(r[2]), "=r"(r[3]) : "r"(addr));
}
__device__ __forceinline__ void ldm_x4_t(uint32_t r[4], uint32_t addr) {
    asm volatile("ldmatrix.sync.aligned.m8n8.x4.trans.shared.b16 {%0,%1,%2,%3}, [%4];\n"
        : "=r"(r[0]), "=r"(r[1]), "=r"(r[2]), "=r"(r[3]) : "r"(addr));
}
__device__ __forceinline__ uint32_t packf(float a, float b) {
    __half2 h = __floats2half2_rn(a, b);
    return *(uint32_t*)&h;
}
__device__ __forceinline__ void mma16816(float c[4], const uint32_t a[4], const uint32_t b0, const uint32_t b1) {
    asm volatile(
        "mma.sync.aligned.m16n8k16.row.col.f32.f16.f16.f32 "
        "{%0,%1,%2,%3},{%4,%5,%6,%7},{%8,%9},{%0,%1,%2,%3};\n"
        : "+f"(c[0]), "+f"(c[1]), "+f"(c[2]), "+f"(c[3])
        : "r"(a[0]), "r"(a[1]), "r"(a[2]), "r"(a[3]), "r"(b0), "r"(b1));
}

// ---------------- weight fp32 -> fp16 ----------------
__global__ void convert_weights(const float* __restrict__ Wq,
                                const float* __restrict__ Wkv,
                                const float* __restrict__ Wo) {
    int i = blockIdx.x * blockDim.x + threadIdx.x;
    if (i < DIMX * DEMBX)     g_wq[i]  = __float2half(Wq[i]);
    if (i < DIMX * 2 * DEMBX) g_wkv[i] = __float2half(Wkv[i]);
    if (i < DEMBX * DIMX)     g_wo[i]  = __float2half(Wo[i]);
}

// ---------------- fused layernorm (src + ltn) ----------------
__global__ void __launch_bounds__(256) ln_kernel(
    const float* __restrict__ src, const float* __restrict__ ltn,
    const float* __restrict__ gs, const float* __restrict__ bs,
    const float* __restrict__ gl, const float* __restrict__ bl) {
    int row = blockIdx.x;              // 0..66047
    int slab = row / NCTX;
    int r = row - slab * NCTX;
    bool is_ltn = (r >= NSRC);
    const float* x; const float* g; const float* b;
    if (!is_ltn) { x = src + (size_t)(slab * NSRC + r) * DIMX; g = gs; b = bs; }
    else         { x = ltn + (size_t)(slab * NLTN + (r - NSRC)) * DIMX; g = gl; b = bl; }

    int t = threadIdx.x;
    float v0 = x[t], v1 = x[t + 256], v2 = x[t + 512];
    float s = v0 + v1 + v2;
    float s2 = v0 * v0 + v1 * v1 + v2 * v2;
    #pragma unroll
    for (int o = 16; o; o >>= 1) {
        s  += __shfl_xor_sync(0xffffffffu, s, o);
        s2 += __shfl_xor_sync(0xffffffffu, s2, o);
    }
    __shared__ float ss[8], ss2[8];
    int w = t >> 5, l = t & 31;
    if (l == 0) { ss[w] = s; ss2[w] = s2; }
    __syncthreads();
    __shared__ float mv[2];
    if (t == 0) {
        float a = 0.f, a2 = 0.f;
        #pragma unroll
        for (int i = 0; i < 8; i++) { a += ss[i]; a2 += ss2[i]; }
        float mean = a * (1.f / 768.f);
        float var  = a2 * (1.f / 768.f) - mean * mean;
        mv[0] = mean;
        mv[1] = rsqrtf(var + 1e-5f);
    }
    __syncthreads();
    float mean = mv[0], rstd = mv[1];

    __half* out = g_ctx + (size_t)row * DIMX;
    __half* out2 = is_ltn ? (g_ltnc + (size_t)(slab * NLTN + (r - NSRC)) * DIMX) : nullptr;
    float vv[3] = {v0, v1, v2};
    #pragma unroll
    for (int i = 0; i < 3; i++) {
        int c = t + i * 256;
        float y = (vv[i] - mean) * rstd * g[c] + b[c];
        __half h = __float2half(y);
        out[c] = h;
        if (out2) out2[c] = h;
    }
}

// ---------------- fp16 MMA GEMM: 4-stage cp.async ring, 1 sync/iter ----------------
// BM=128, BN=128, BK=32, 256 thr, dynamic smem (4 stages x 18944 B = 75776 B)
// MODE 0: g_q   = g_ltnc @ g_wq   (512  x 512 , K=768)  -> half
// MODE 1: g_kv  = g_ctx  @ g_wkv  (66048x 1024, K=768)  -> half
// MODE 2: dout  = g_att  @ g_wo   (512  x 768 , K=512)  -> float
#define GSTG 4
#define A_HALVES (128 * 40)
#define B_HALVES (32 * 136)
#define STG_HALVES (A_HALVES + B_HALVES)       // 9472
#define GEMM_SMEM_BYTES (GSTG * STG_HALVES * 2) // 75776

template <int MODE>
__global__ void __launch_bounds__(256) gemm_kernel(float* __restrict__ dout) {
    constexpr int N = (MODE == 0) ? 512 : ((MODE == 1) ? 1024 : 768);
    constexpr int K = (MODE == 2) ? 512 : 768;
    const __half* A = (MODE == 0) ? g_ltnc : ((MODE == 1) ? g_ctx : g_att);
    const __half* B = (MODE == 0) ? g_wq  : ((MODE == 1) ? g_wkv : g_wo);
    __half* Ch      = (MODE == 0) ? g_q   : g_kv;

    extern __shared__ __half dyn[];

    const int m0 = blockIdx.y * 128, n0 = blockIdx.x * 128;
    const int tid = threadIdx.x;
    const int warp = tid >> 5, lane = tid & 31;
    const int wm = (warp >> 1) * 32, wn = (warp & 1) * 64;
    const int r = lane >> 2, q = lane & 3;
    const int rr = lane & 7, tt = lane >> 3;   // ldmatrix lane decomposition

    float acc[2][8][4];
    #pragma unroll
    for (int i = 0; i < 2; i++)
        #pragma unroll
        for (int j = 0; j < 8; j++)
            #pragma unroll
            for (int k = 0; k < 4; k++) acc[i][j][k] = 0.f;

    // per-thread fixed load offsets
    const int a_row = tid >> 2,              a_col = (tid & 3) * 8;       // +64 rows on 2nd
    const int b_row = tid >> 4,              b_col = (tid & 15) * 8;      // +16 rows on 2nd

    auto load_stage = [&](int s, int k0) {
        __half* As = dyn + s * STG_HALVES;
        __half* Bs = As + A_HALVES;
        cp16(smem_u32(&As[a_row * 40 + a_col]),
             A + (size_t)(m0 + a_row) * K + k0 + a_col);
        cp16(smem_u32(&As[(a_row + 64) * 40 + a_col]),
             A + (size_t)(m0 + a_row + 64) * K + k0 + a_col);
        cp16(smem_u32(&Bs[b_row * 136 + b_col]),
             B + (size_t)(k0 + b_row) * N + n0 + b_col);
        cp16(smem_u32(&Bs[(b_row + 16) * 136 + b_col]),
             B + (size_t)(k0 + b_row + 16) * N + n0 + b_col);
    };

    constexpr int NIT = K / 32;
    load_stage(0, 0);  CP_COMMIT();
    load_stage(1, 32); CP_COMMIT();
    load_stage(2, 64); CP_COMMIT();

    for (int it = 0; it < NIT; ++it) {
        // ensure stage `it` is resident (keep up to 2 younger groups in flight)
        if (it + 2 < NIT)      { CP_WAIT2(); }
        else if (it + 1 < NIT) { CP_WAIT1(); }
        else                   { CP_WAIT0(); }
        __syncthreads();   // publishes stage it; protects rewrite of stage it-1

        if (it + 3 < NIT) { load_stage((it + 3) & (GSTG - 1), (it + 3) * 32); CP_COMMIT(); }

        const int s = it & (GSTG - 1);
        __half* As = dyn + s * STG_HALVES;
        __half* Bs = As + A_HALVES;

        uint32_t af[2][2][4];
        #pragma unroll
        for (int mt = 0; mt < 2; mt++)
            #pragma unroll
            for (int kt = 0; kt < 2; kt++) {
                int row = wm + 16 * mt + (tt & 1) * 8 + rr;
                int col = kt * 16 + (tt >> 1) * 8;
                ldm_x4(af[mt][kt], smem_u32(&As[row * 40 + col]));
            }
        #pragma unroll
        for (int kt = 0; kt < 2; kt++) {
            uint32_t bf[4][4];
            #pragma unroll
            for (int np = 0; np < 4; np++) {
                int krow = kt * 16 + (tt & 1) * 8 + rr;
                int col  = wn + np * 16 + (tt >> 1) * 8;
                ldm_x4_t(bf[np], smem_u32(&Bs[krow * 136 + col]));
            }
            #pragma unroll
            for (int np = 0; np < 4; np++)
                #pragma unroll
                for (int mt = 0; mt < 2; mt++) {
                    mma16816(acc[mt][2 * np],     af[mt][kt], bf[np][0], bf[np][1]);
                    mma16816(acc[mt][2 * np + 1], af[mt][kt], bf[np][2], bf[np][3]);
                }
        }
    }

    #pragma unroll
    for (int mt = 0; mt < 2; mt++)
        #pragma unroll
        for (int nt = 0; nt < 8; nt++) {
            int row = m0 + wm + 16 * mt + r;
            int col = n0 + wn + nt * 8 + q * 2;
            if (MODE == 2) {
                *(float2*)&dout[(size_t)row * N + col] =
                    make_float2(acc[mt][nt][0], acc[mt][nt][1]);
                *(float2*)&dout[(size_t)(row + 8) * N + col] =
                    make_float2(acc[mt][nt][2], acc[mt][nt][3]);
            } else {
                *(__half2*)&Ch[(size_t)row * N + col] =
                    __floats2half2_rn(acc[mt][nt][0], acc[mt][nt][1]);
                *(__half2*)&Ch[(size_t)(row + 8) * N + col] =
                    __floats2half2_rn(acc[mt][nt][2], acc[mt][nt][3]);
            }
        }
}

// ---------------- split-context flash attention ----------------
__global__ void __launch_bounds__(128) attn_kernel() {
    const int split = blockIdx.x >> 6;
    const int sh = blockIdx.x & 63;
    const int slab = sh >> 3, h = sh & 7;
    __shared__ __half Qs[64][72];
    __shared__ __half Ks[2][64][72];
    __shared__ __half Vs[2][64][72];
    const int tid = threadIdx.x, warp = tid >> 5, lane = tid & 31;
    const int r = lane >> 2, q = lane & 3;
    const int rr = lane & 7, tt = lane >> 3;

    for (int i = tid; i < 512; i += 128) {
        int row = i >> 3, c = (i & 7) * 8;
        *(uint4*)&Qs[row][c] =
            *(const uint4*)&g_q[(size_t)(slab * 64 + row) * DEMBX + h * 64 + c];
    }
    __syncthreads();

    uint32_t qa[4][4];
    #pragma unroll
    for (int kt = 0; kt < 4; kt++) {
        int row = warp * 16 + (tt & 1) * 8 + rr;
        int col = kt * 16 + (tt >> 1) * 8;
        ldm_x4(qa[kt], smem_u32(&Qs[row][col]));
    }

    float o[8][4];
    #pragma unroll
    for (int nt = 0; nt < 8; nt++)
        #pragma unroll
        for (int i = 0; i < 4; i++) o[nt][i] = 0.f;
    float m0 = -1e30f, m1 = -1e30f, l0 = 0.f, l1 = 0.f;

    const size_t rowbase = (size_t)slab * NCTX + (size_t)split * TILES_PER_SPLIT * 64;
    auto load_kv = [&](int s, int c0) {
        #pragma unroll
        for (int i = 0; i < 4; i++) {
            int id = tid + i * 128;
            int row = id >> 3, cc = (id & 7) * 8;
            const __half* srcp = g_kv + (rowbase + c0 + row) * 1024 + h * 64 + cc;
            cp16(smem_u32(&Ks[s][row][cc]), srcp);
            cp16(smem_u32(&Vs[s][row][cc]), srcp + 512);
        }
    };

    load_kv(0, 0);
    CP_COMMIT();
    const int NIT = TILES_PER_SPLIT;
    for (int it = 0; it < NIT; ++it) {
        CP_WAIT0();
        __syncthreads();
        if (it + 1 < NIT) { load_kv((it + 1) & 1, (it + 1) * 64); CP_COMMIT(); }
        int s = it & 1;

        float sf[8][4];
        #pragma unroll
        for (int nt = 0; nt < 8; nt++)
            #pragma unroll
            for (int i = 0; i < 4; i++) sf[nt][i] = 0.f;
        #pragma unroll
        for (int kt = 0; kt < 4; kt++) {
            uint32_t kb[4][4];
            #pragma unroll
            for (int np = 0; np < 4; np++) {
                int nrow = np * 16 + (tt >> 1) * 8 + rr;
                int col  = kt * 16 + (tt & 1) * 8;
                ldm_x4(kb[np], smem_u32(&Ks[s][nrow][col]));
            }
            #pragma unroll
            for (int np = 0; np < 4; np++) {
                mma16816(sf[2 * np],     qa[kt], kb[np][0], kb[np][1]);
                mma16816(sf[2 * np + 1], qa[kt], kb[np][2], kb[np][3]);
            }
        }
        float mn0 = m0, mn1 = m1;
        #pragma unroll
        for (int nt = 0; nt < 8; nt++) {
            sf[nt][0] *= 0.125f; sf[nt][1] *= 0.125f;
            sf[nt][2] *= 0.125f; sf[nt][3] *= 0.125f;
            mn0 = fmaxf(mn0, fmaxf(sf[nt][0], sf[nt][1]));
            mn1 = fmaxf(mn1, fmaxf(sf[nt][2], sf[nt][3]));
        }
        mn0 = fmaxf(mn0, __shfl_xor_sync(0xffffffffu, mn0, 1));
        mn0 = fmaxf(mn0, __shfl_xor_sync(0xffffffffu, mn0, 2));
        mn1 = fmaxf(mn1, __shfl_xor_sync(0xffffffffu, mn1, 1));
        mn1 = fmaxf(mn1, __shfl_xor_sync(0xffffffffu, mn1, 2));
        float a0 = __expf(m0 - mn0), a1 = __expf(m1 - mn1);
        float rs0 = 0.f, rs1 = 0.f;
        #pragma unroll
        for (int nt = 0; nt < 8; nt++) {
            sf[nt][0] = __expf(sf[nt][0] - mn0);
            sf[nt][1] = __expf(sf[nt][1] - mn0);
            sf[nt][2] = __expf(sf[nt][2] - mn1);
            sf[nt][3] = __expf(sf[nt][3] - mn1);
            rs0 += sf[nt][0] + sf[nt][1];
            rs1 += sf[nt][2] + sf[nt][3];
        }
        rs0 += __shfl_xor_sync(0xffffffffu, rs0, 1);
        rs0 += __shfl_xor_sync(0xffffffffu, rs0, 2);
        rs1 += __shfl_xor_sync(0xffffffffu, rs1, 1);
        rs1 += __shfl_xor_sync(0xffffffffu, rs1, 2);
        l0 = l0 * a0 + rs0; l1 = l1 * a1 + rs1;
        m0 = mn0; m1 = mn1;
        #pragma unroll
        for (int nt = 0; nt < 8; nt++) {
            o[nt][0] *= a0; o[nt][1] *= a0;
            o[nt][2] *= a1; o[nt][3] *= a1;
        }
        uint32_t pa[4][4];
        #pragma unroll
        for (int t2 = 0; t2 < 4; t2++) {
            pa[t2][0] = packf(sf[2 * t2][0],     sf[2 * t2][1]);
            pa[t2][1] = packf(sf[2 * t2][2],     sf[2 * t2][3]);
            pa[t2][2] = packf(sf[2 * t2 + 1][0], sf[2 * t2 + 1][1]);
            pa[t2][3] = packf(sf[2 * t2 + 1][2], sf[2 * t2 + 1][3]);
        }
        #pragma unroll
        for (int kt = 0; kt < 4; kt++) {
            uint32_t vb[4][4];
            #pragma unroll
            for (int np = 0; np < 4; np++) {
                int krow = kt * 16 + (tt & 1) * 8 + rr;
                int col  = np * 16 + (tt >> 1) * 8;
                ldm_x4_t(vb[np], smem_u32(&Vs[s][krow][col]));
            }
            #pragma unroll
            for (int np = 0; np < 4; np++) {
                mma16816(o[2 * np],     pa[kt], vb[np][0], vb[np][1]);
                mma16816(o[2 * np + 1], pa[kt], vb[np][2], vb[np][3]);
            }
        }
    }

    float* po = g_po + (size_t)blockIdx.x * 4096;
    #pragma unroll
    for (int nt = 0; nt < 8; nt++) {
        int row = warp * 16 + r;
        int col = nt * 8 + q * 2;
        *(float2*)&po[row * 64 + col]       = make_float2(o[nt][0], o[nt][1]);
        *(float2*)&po[(row + 8) * 64 + col] = make_float2(o[nt][2], o[nt][3]);
    }
    if (q == 0) {
        int row = warp * 16 + r;
        g_pm[blockIdx.x * 64 + row]     = m0;
        g_pm[blockIdx.x * 64 + row + 8] = m1;
        g_pl[blockIdx.x * 64 + row]     = l0;
        g_pl[blockIdx.x * 64 + row + 8] = l1;
    }
}

// ---------------- combine split partials -> g_att (fp16) ----------------
__global__ void __launch_bounds__(128) combine_kernel() {
    const int sh = blockIdx.x;
    const int slab = sh >> 3, h = sh & 7;
    __shared__ float wsh[NSPLIT][64];
    __shared__ float invl[64];
    int tid = threadIdx.x;
    if (tid < 64) {
        float m[NSPLIT], l[NSPLIT];
        float M = -1e30f;
        #pragma unroll
        for (int s = 0; s < NSPLIT; s++) {
            m[s] = g_pm[(s * 64 + sh) * 64 + tid];
            l[s] = g_pl[(s * 64 + sh) * 64 + tid];
            M = fmaxf(M, m[s]);
        }
        float L = 0.f;
        #pragma unroll
        for (int s = 0; s < NSPLIT; s++) {
            float w = __expf(m[s] - M);
            wsh[s][tid] = w;
            L += w * l[s];
        }
        invl[tid] = 1.f / L;
    }
    __syncthreads();
    for (int i = tid; i < 4096; i += 128) {
        int row = i >> 6, col = i & 63;
        float acc = 0.f;
        #pragma unroll
        for (int s = 0; s < NSPLIT; s++)
            acc += wsh[s][row] * g_po[(size_t)(s * 64 + sh) * 4096 + i];
        g_att[(size_t)(slab * 64 + row) * DEMBX + h * 64 + col] =
            __float2half(acc * invl[row]);
    }
}

// ---------------- launch ----------------
extern "C" void kernel_launch(void* const* d_in, const int* in_sizes, int n_in,
                              void* d_out, int out_size) {
    const float* src  = (const float*)d_in[0];
    const float* ltn  = (const float*)d_in[1];
    const float* gs   = (const float*)d_in[2];
    const float* bs   = (const float*)d_in[3];
    const float* gl   = (const float*)d_in[4];
    const float* bl   = (const float*)d_in[5];
    const float* Wq   = (const float*)d_in[6];
    const float* Wkv  = (const float*)d_in[7];
    const float* Wo   = (const float*)d_in[8];
    float* out = (float*)d_out;

    static bool attr_done = false;
    if (!attr_done) {
        cudaFuncSetAttribute(gemm_kernel<0>, cudaFuncAttributeMaxDynamicSharedMemorySize, GEMM_SMEM_BYTES);
        cudaFuncSetAttribute(gemm_kernel<1>, cudaFuncAttributeMaxDynamicSharedMemorySize, GEMM_SMEM_BYTES);
        cudaFuncSetAttribute(gemm_kernel<2>, cudaFuncAttributeMaxDynamicSharedMemorySize, GEMM_SMEM_BYTES);
        attr_done = true;
    }

    convert_weights<<<(DIMX * 2 * DEMBX + 255) / 256, 256>>>(Wq, Wkv, Wo);
    ln_kernel<<<MROWS, 256>>>(src, ltn, gs, bs, gl, bl);
    gemm_kernel<0><<<dim3(512 / 128, 512 / 128), 256, GEMM_SMEM_BYTES>>>(nullptr);     // Q
    gemm_kernel<1><<<dim3(1024 / 128, MROWS / 128), 256, GEMM_SMEM_BYTES>>>(nullptr);  // KV
    attn_kernel<<<NSPLIT * 64, 128>>>();
    combine_kernel<<<64, 128>>>();
    gemm_kernel<2><<<dim3(768 / 128, 512 / 128), 256, GEMM_SMEM_BYTES>>>(out);         // out proj
}

// round 8
// speedup vs baseline: 1.0007x; 1.0007x over previous
#include <cuda_runtime.h>
#include <cuda_fp16.h>
#include <cstdint>

#define DIMX 768
#define DEMBX 512
#define NSRC 8192
#define NLTN 64
#define NSLAB 8
#define NCTX 8256                 // per-slab context rows (src + ltn)
#define MROWS (NSLAB * NCTX)      // 66048
#define NSPLIT 3
#define TILES_PER_SPLIT 43        // 129 tiles / 3

// ---------------- scratch (static device globals: allowed) ----------------
__device__ __half g_ctx[(size_t)MROWS * DIMX];        // normalized context, fp16
__device__ __half g_ltnc[(size_t)NSLAB * NLTN * DIMX];// compact normalized ltn
__device__ __half g_wq[DIMX * DEMBX];
__device__ __half g_wkv[DIMX * 2 * DEMBX];
__device__ __half g_wo[DEMBX * DIMX];
__device__ __half g_q[NSLAB * NLTN * DEMBX];
__device__ __half g_kv[(size_t)MROWS * 2 * DEMBX];    // K | V
__device__ __half g_att[NSLAB * NLTN * DEMBX];
__device__ float g_po[NSPLIT * 64 * 64 * 64];
__device__ float g_pm[NSPLIT * 64 * 64];
__device__ float g_pl[NSPLIT * 64 * 64];

// ---------------- helpers ----------------
__device__ __forceinline__ uint32_t smem_u32(const void* p) {
    return (uint32_t)__cvta_generic_to_shared(p);
}
__device__ __forceinline__ void cp16(uint32_t s, const void* g) {
    asm volatile("cp.async.cg.shared.global [%0], [%1], 16;\n" :: "r"(s), "l"(g));
}
#define CP_COMMIT() asm volatile("cp.async.commit_group;\n")
#define CP_WAIT0()  asm volatile("cp.async.wait_group 0;\n")
#define CP_WAIT1()  asm volatile("cp.async.wait_group 1;\n")
#define CP_WAIT2()  asm volatile("cp.async.wait_group 2;\n")

__device__ __forceinline__ void ldm_x4(uint32_t r[4], uint32_t addr) {
    asm volatile("ldmatrix.sync.aligned.m8n8.x4.shared.b16 {%0,%1,%2,%3}, [%4];\n"
        : "=r"(r[0]), "=r"(r[1]), "=r"(r[2]), "=r"(r[3]) : "r"(addr));
}
__device__ __forceinline__ void ldm_x4_t(uint32_t r[4], uint32_t addr) {
    asm volatile("ldmatrix.sync.aligned.m8n8.x4.trans.shared.b16 {%0,%1,%2,%3}, [%4];\n"
        : "=r"(r[0]), "=r"(r[1]), "=r"(r[2]), "=r"(r[3]) : "r"(addr));
}
__device__ __forceinline__ uint32_t packf(float a, float b) {
    __half2 h = __floats2half2_rn(a, b);
    return *(uint32_t*)&h;
}
__device__ __forceinline__ void mma16816(float c[4], const uint32_t a[4], const uint32_t b0, const uint32_t b1) {
    asm volatile(
        "mma.sync.aligned.m16n8k16.row.col.f32.f16.f16.f32 "
        "{%0,%1,%2,%3},{%4,%5,%6,%7},{%8,%9},{%0,%1,%2,%3};\n"
        : "+f"(c[0]), "+f"(c[1]), "+f"(c[2]), "+f"(c[3])
        : "r"(a[0]), "r"(a[1]), "r"(a[2]), "r"(a[3]), "r"(b0), "r"(b1));
}

// ---------------- weight fp32 -> fp16 ----------------
__global__ void convert_weights(const float* __restrict__ Wq,
                                const float* __restrict__ Wkv,
                                const float* __restrict__ Wo) {
    int i = blockIdx.x * blockDim.x + threadIdx.x;
    if (i < DIMX * DEMBX)     g_wq[i]  = __float2half(Wq[i]);
    if (i < DIMX * 2 * DEMBX) g_wkv[i] = __float2half(Wkv[i]);
    if (i < DEMBX * DIMX)     g_wo[i]  = __float2half(Wo[i]);
}

// ---------------- fused layernorm (src + ltn) ----------------
__global__ void __launch_bounds__(256) ln_kernel(
    const float* __restrict__ src, const float* __restrict__ ltn,
    const float* __restrict__ gs, const float* __restrict__ bs,
    const float* __restrict__ gl, const float* __restrict__ bl) {
    int row = blockIdx.x;              // 0..66047
    int slab = row / NCTX;
    int r = row - slab * NCTX;
    bool is_ltn = (r >= NSRC);
    const float* x; const float* g; const float* b;
    if (!is_ltn) { x = src + (size_t)(slab * NSRC + r) * DIMX; g = gs; b = bs; }
    else         { x = ltn + (size_t)(slab * NLTN + (r - NSRC)) * DIMX; g = gl; b = bl; }

    int t = threadIdx.x;
    float v0 = x[t], v1 = x[t + 256], v2 = x[t + 512];
    float s = v0 + v1 + v2;
    float s2 = v0 * v0 + v1 * v1 + v2 * v2;
    #pragma unroll
    for (int o = 16; o; o >>= 1) {
        s  += __shfl_xor_sync(0xffffffffu, s, o);
        s2 += __shfl_xor_sync(0xffffffffu, s2, o);
    }
    __shared__ float ss[8], ss2[8];
    int w = t >> 5, l = t & 31;
    if (l == 0) { ss[w] = s; ss2[w] = s2; }
    __syncthreads();
    __shared__ float mv[2];
    if (t == 0) {
        float a = 0.f, a2 = 0.f;
        #pragma unroll
        for (int i = 0; i < 8; i++) { a += ss[i]; a2 += ss2[i]; }
        float mean = a * (1.f / 768.f);
        float var  = a2 * (1.f / 768.f) - mean * mean;
        mv[0] = mean;
        mv[1] = rsqrtf(var + 1e-5f);
    }
    __syncthreads();
    float mean = mv[0], rstd = mv[1];

    __half* out = g_ctx + (size_t)row * DIMX;
    __half* out2 = is_ltn ? (g_ltnc + (size_t)(slab * NLTN + (r - NSRC)) * DIMX) : nullptr;
    float vv[3] = {v0, v1, v2};
    #pragma unroll
    for (int i = 0; i < 3; i++) {
        int c = t + i * 256;
        float y = (vv[i] - mean) * rstd * g[c] + b[c];
        __half h = __float2half(y);
        out[c] = h;
        if (out2) out2[c] = h;
    }
}

// ---------------- fp16 MMA GEMM: 4-stage cp.async ring, 1 sync/iter ----------------
// BM=128, BN=128, BK=32, 256 thr, dynamic smem (4 stages x 18944 B = 75776 B)
// MODE 0: g_q   = g_ltnc @ g_wq   (512  x 512 , K=768)  -> half
// MODE 1: g_kv  = g_ctx  @ g_wkv  (66048x 1024, K=768)  -> half
// MODE 2: dout  = g_att  @ g_wo   (512  x 768 , K=512)  -> float
#define GSTG 4
#define A_HALVES (128 * 40)
#define B_HALVES (32 * 136)
#define STG_HALVES (A_HALVES + B_HALVES)       // 9472
#define GEMM_SMEM_BYTES (GSTG * STG_HALVES * 2) // 75776

template <int MODE>
__global__ void __launch_bounds__(256) gemm_kernel(float* __restrict__ dout) {
    constexpr int N = (MODE == 0) ? 512 : ((MODE == 1) ? 1024 : 768);
    constexpr int K = (MODE == 2) ? 512 : 768;
    const __half* A = (MODE == 0) ? g_ltnc : ((MODE == 1) ? g_ctx : g_att);
    const __half* B = (MODE == 0) ? g_wq  : ((MODE == 1) ? g_wkv : g_wo);
    __half* Ch      = (MODE == 0) ? g_q   : g_kv;

    extern __shared__ __half dyn[];

    const int m0 = blockIdx.y * 128, n0 = blockIdx.x * 128;
    const int tid = threadIdx.x;
    const int warp = tid >> 5, lane = tid & 31;
    const int wm = (warp >> 1) * 32, wn = (warp & 1) * 64;
    const int r = lane >> 2, q = lane & 3;
    const int rr = lane & 7, tt = lane >> 3;   // ldmatrix lane decomposition

    float acc[2][8][4];
    #pragma unroll
    for (int i = 0; i < 2; i++)
        #pragma unroll
        for (int j = 0; j < 8; j++)
            #pragma unroll
            for (int k = 0; k < 4; k++) acc[i][j][k] = 0.f;

    // per-thread fixed load offsets
    const int a_row = tid >> 2,              a_col = (tid & 3) * 8;       // +64 rows on 2nd
    const int b_row = tid >> 4,              b_col = (tid & 15) * 8;      // +16 rows on 2nd

    auto load_stage = [&](int s, int k0) {
        __half* As = dyn + s * STG_HALVES;
        __half* Bs = As + A_HALVES;
        cp16(smem_u32(&As[a_row * 40 + a_col]),
             A + (size_t)(m0 + a_row) * K + k0 + a_col);
        cp16(smem_u32(&As[(a_row + 64) * 40 + a_col]),
             A + (size_t)(m0 + a_row + 64) * K + k0 + a_col);
        cp16(smem_u32(&Bs[b_row * 136 + b_col]),
             B + (size_t)(k0 + b_row) * N + n0 + b_col);
        cp16(smem_u32(&Bs[(b_row + 16) * 136 + b_col]),
             B + (size_t)(k0 + b_row + 16) * N + n0 + b_col);
    };

    constexpr int NIT = K / 32;
    load_stage(0, 0);  CP_COMMIT();
    load_stage(1, 32); CP_COMMIT();
    load_stage(2, 64); CP_COMMIT();

    for (int it = 0; it < NIT; ++it) {
        // ensure stage `it` is resident (keep up to 2 younger groups in flight)
        if (it + 2 < NIT)      { CP_WAIT2(); }
        else if (it + 1 < NIT) { CP_WAIT1(); }
        else                   { CP_WAIT0(); }
        __syncthreads();   // publishes stage it; protects rewrite of stage it-1

        if (it + 3 < NIT) { load_stage((it + 3) & (GSTG - 1), (it + 3) * 32); CP_COMMIT(); }

        const int s = it & (GSTG - 1);
        __half* As = dyn + s * STG_HALVES;
        __half* Bs = As + A_HALVES;

        uint32_t af[2][2][4];
        #pragma unroll
        for (int mt = 0; mt < 2; mt++)
            #pragma unroll
            for (int kt = 0; kt < 2; kt++) {
                int row = wm + 16 * mt + (tt & 1) * 8 + rr;
                int col = kt * 16 + (tt >> 1) * 8;
                ldm_x4(af[mt][kt], smem_u32(&As[row * 40 + col]));
            }
        #pragma unroll
        for (int kt = 0; kt < 2; kt++) {
            uint32_t bf[4][4];
            #pragma unroll
            for (int np = 0; np < 4; np++) {
                int krow = kt * 16 + (tt & 1) * 8 + rr;
                int col  = wn + np * 16 + (tt >> 1) * 8;
                ldm_x4_t(bf[np], smem_u32(&Bs[krow * 136 + col]));
            }
            #pragma unroll
            for (int np = 0; np < 4; np++)
                #pragma unroll
                for (int mt = 0; mt < 2; mt++) {
                    mma16816(acc[mt][2 * np],     af[mt][kt], bf[np][0], bf[np][1]);
                    mma16816(acc[mt][2 * np + 1], af[mt][kt], bf[np][2], bf[np][3]);
                }
        }
    }

    #pragma unroll
    for (int mt = 0; mt < 2; mt++)
        #pragma unroll
        for (int nt = 0; nt < 8; nt++) {
            int row = m0 + wm + 16 * mt + r;
            int col = n0 + wn + nt * 8 + q * 2;
            if (MODE == 2) {
                *(float2*)&dout[(size_t)row * N + col] =
                    make_float2(acc[mt][nt][0], acc[mt][nt][1]);
                *(float2*)&dout[(size_t)(row + 8) * N + col] =
                    make_float2(acc[mt][nt][2], acc[mt][nt][3]);
            } else {
                *(__half2*)&Ch[(size_t)row * N + col] =
                    __floats2half2_rn(acc[mt][nt][0], acc[mt][nt][1]);
                *(__half2*)&Ch[(size_t)(row + 8) * N + col] =
                    __floats2half2_rn(acc[mt][nt][2], acc[mt][nt][3]);
            }
        }
}

// ---------------- split-context flash attention ----------------
__global__ void __launch_bounds__(128) attn_kernel() {
    const int split = blockIdx.x >> 6;
    const int sh = blockIdx.x & 63;
    const int slab = sh >> 3, h = sh & 7;
    __shared__ __half Qs[64][72];
    __shared__ __half Ks[2][64][72];
    __shared__ __half Vs[2][64][72];
    const int tid = threadIdx.x, warp = tid >> 5, lane = tid & 31;
    const int r = lane >> 2, q = lane & 3;
    const int rr = lane & 7, tt = lane >> 3;

    for (int i = tid; i < 512; i += 128) {
        int row = i >> 3, c = (i & 7) * 8;
        *(uint4*)&Qs[row][c] =
            *(const uint4*)&g_q[(size_t)(slab * 64 + row) * DEMBX + h * 64 + c];
    }
    __syncthreads();

    uint32_t qa[4][4];
    #pragma unroll
    for (int kt = 0; kt < 4; kt++) {
        int row = warp * 16 + (tt & 1) * 8 + rr;
        int col = kt * 16 + (tt >> 1) * 8;
        ldm_x4(qa[kt], smem_u32(&Qs[row][col]));
    }

    float o[8][4];
    #pragma unroll
    for (int nt = 0; nt < 8; nt++)
        #pragma unroll
        for (int i = 0; i < 4; i++) o[nt][i] = 0.f;
    float m0 = -1e30f, m1 = -1e30f, l0 = 0.f, l1 = 0.f;

    const size_t rowbase = (size_t)slab * NCTX + (size_t)split * TILES_PER_SPLIT * 64;
    auto load_kv = [&](int s, int c0) {
        #pragma unroll
        for (int i = 0; i < 4; i++) {
            int id = tid + i * 128;
            int row = id >> 3, cc = (id & 7) * 8;
            const __half* srcp = g_kv + (rowbase + c0 + row) * 1024 + h * 64 + cc;
            cp16(smem_u32(&Ks[s][row][cc]), srcp);
            cp16(smem_u32(&Vs[s][row][cc]), srcp + 512);
        }
    };

    load_kv(0, 0);
    CP_COMMIT();
    const int NIT = TILES_PER_SPLIT;
    for (int it = 0; it < NIT; ++it) {
        CP_WAIT0();
        __syncthreads();
        if (it + 1 < NIT) { load_kv((it + 1) & 1, (it + 1) * 64); CP_COMMIT(); }
        int s = it & 1;

        float sf[8][4];
        #pragma unroll
        for (int nt = 0; nt < 8; nt++)
            #pragma unroll
            for (int i = 0; i < 4; i++) sf[nt][i] = 0.f;
        #pragma unroll
        for (int kt = 0; kt < 4; kt++) {
            uint32_t kb[4][4];
            #pragma unroll
            for (int np = 0; np < 4; np++) {
                int nrow = np * 16 + (tt >> 1) * 8 + rr;
                int col  = kt * 16 + (tt & 1) * 8;
                ldm_x4(kb[np], smem_u32(&Ks[s][nrow][col]));
            }
            #pragma unroll
            for (int np = 0; np < 4; np++) {
                mma16816(sf[2 * np],     qa[kt], kb[np][0], kb[np][1]);
                mma16816(sf[2 * np + 1], qa[kt], kb[np][2], kb[np][3]);
            }
        }
        float mn0 = m0, mn1 = m1;
        #pragma unroll
        for (int nt = 0; nt < 8; nt++) {
            sf[nt][0] *= 0.125f; sf[nt][1] *= 0.125f;
            sf[nt][2] *= 0.125f; sf[nt][3] *= 0.125f;
            mn0 = fmaxf(mn0, fmaxf(sf[nt][0], sf[nt][1]));
            mn1 = fmaxf(mn1, fmaxf(sf[nt][2], sf[nt][3]));
        }
        mn0 = fmaxf(mn0, __shfl_xor_sync(0xffffffffu, mn0, 1));
        mn0 = fmaxf(mn0, __shfl_xor_sync(0xffffffffu, mn0, 2));
        mn1 = fmaxf(mn1, __shfl_xor_sync(0xffffffffu, mn1, 1));
        mn1 = fmaxf(mn1, __shfl_xor_sync(0xffffffffu, mn1, 2));
        float a0 = __expf(m0 - mn0), a1 = __expf(m1 - mn1);
        float rs0 = 0.f, rs1 = 0.f;
        #pragma unroll
        for (int nt = 0; nt < 8; nt++) {
            sf[nt][0] = __expf(sf[nt][0] - mn0);
            sf[nt][1] = __expf(sf[nt][1] - mn0);
            sf[nt][2] = __expf(sf[nt][2] - mn1);
            sf[nt][3] = __expf(sf[nt][3] - mn1);
            rs0 += sf[nt][0] + sf[nt][1];
            rs1 += sf[nt][2] + sf[nt][3];
        }
        rs0 += __shfl_xor_sync(0xffffffffu, rs0, 1);
        rs0 += __shfl_xor_sync(0xffffffffu, rs0, 2);
        rs1 += __shfl_xor_sync(0xffffffffu, rs1, 1);
        rs1 += __shfl_xor_sync(0xffffffffu, rs1, 2);
        l0 = l0 * a0 + rs0; l1 = l1 * a1 + rs1;
        m0 = mn0; m1 = mn1;
        #pragma unroll
        for (int nt = 0; nt < 8; nt++) {
            o[nt][0] *= a0; o[nt][1] *= a0;
            o[nt][2] *= a1; o[nt][3] *= a1;
        }
        uint32_t pa[4][4];
        #pragma unroll
        for (int t2 = 0; t2 < 4; t2++) {
            pa[t2][0] = packf(sf[2 * t2][0],     sf[2 * t2][1]);
            pa[t2][1] = packf(sf[2 * t2][2],     sf[2 * t2][3]);
            pa[t2][2] = packf(sf[2 * t2 + 1][0], sf[2 * t2 + 1][1]);
            pa[t2][3] = packf(sf[2 * t2 + 1][2], sf[2 * t2 + 1][3]);
        }
        #pragma unroll
        for (int kt = 0; kt < 4; kt++) {
            uint32_t vb[4][4];
            #pragma unroll
            for (int np = 0; np < 4; np++) {
                int krow = kt * 16 + (tt & 1) * 8 + rr;
                int col  = np * 16 + (tt >> 1) * 8;
                ldm_x4_t(vb[np], smem_u32(&Vs[s][krow][col]));
            }
            #pragma unroll
            for (int np = 0; np < 4; np++) {
                mma16816(o[2 * np],     pa[kt], vb[np][0], vb[np][1]);
                mma16816(o[2 * np + 1], pa[kt], vb[np][2], vb[np][3]);
            }
        }
    }

    float* po = g_po + (size_t)blockIdx.x * 4096;
    #pragma unroll
    for (int nt = 0; nt < 8; nt++) {
        int row = warp * 16 + r;
        int col = nt * 8 + q * 2;
        *(float2*)&po[row * 64 + col]       = make_float2(o[nt][0], o[nt][1]);
        *(float2*)&po[(row + 8) * 64 + col] = make_float2(o[nt][2], o[nt][3]);
    }
    if (q == 0) {
        int row = warp * 16 + r;
        g_pm[blockIdx.x * 64 + row]     = m0;
        g_pm[blockIdx.x * 64 + row + 8] = m1;
        g_pl[blockIdx.x * 64 + row]     = l0;
        g_pl[blockIdx.x * 64 + row + 8] = l1;
    }
}

// ---------------- combine split partials -> g_att (fp16) ----------------
__global__ void __launch_bounds__(128) combine_kernel() {
    const int sh = blockIdx.x;
    const int slab = sh >> 3, h = sh & 7;
    __shared__ float wsh[NSPLIT][64];
    __shared__ float invl[64];
    int tid = threadIdx.x;
    if (tid < 64) {
        float m[NSPLIT], l[NSPLIT];
        float M = -1e30f;
        #pragma unroll
        for (int s = 0; s < NSPLIT; s++) {
            m[s] = g_pm[(s * 64 + sh) * 64 + tid];
            l[s] = g_pl[(s * 64 + sh) * 64 + tid];
            M = fmaxf(M, m[s]);
        }
        float L = 0.f;
        #pragma unroll
        for (int s = 0; s < NSPLIT; s++) {
            float w = __expf(m[s] - M);
            wsh[s][tid] = w;
            L += w * l[s];
        }
        invl[tid] = 1.f / L;
    }
    __syncthreads();
    for (int i = tid; i < 4096; i += 128) {
        int row = i >> 6, col = i & 63;
        float acc = 0.f;
        #pragma unroll
        for (int s = 0; s < NSPLIT; s++)
            acc += wsh[s][row] * g_po[(size_t)(s * 64 + sh) * 4096 + i];
        g_att[(size_t)(slab * 64 + row) * DEMBX + h * 64 + col] =
            __float2half(acc * invl[row]);
    }
}

// ---------------- launch ----------------
extern "C" void kernel_launch(void* const* d_in, const int* in_sizes, int n_in,
                              void* d_out, int out_size) {
    const float* src  = (const float*)d_in[0];
    const float* ltn  = (const float*)d_in[1];
    const float* gs   = (const float*)d_in[2];
    const float* bs   = (const float*)d_in[3];
    const float* gl   = (const float*)d_in[4];
    const float* bl   = (const float*)d_in[5];
    const float* Wq   = (const float*)d_in[6];
    const float* Wkv  = (const float*)d_in[7];
    const float* Wo   = (const float*)d_in[8];
    float* out = (float*)d_out;

    static bool attr_done = false;
    if (!attr_done) {
        cudaFuncSetAttribute(gemm_kernel<0>, cudaFuncAttributeMaxDynamicSharedMemorySize, GEMM_SMEM_BYTES);
        cudaFuncSetAttribute(gemm_kernel<1>, cudaFuncAttributeMaxDynamicSharedMemorySize, GEMM_SMEM_BYTES);
        cudaFuncSetAttribute(gemm_kernel<2>, cudaFuncAttributeMaxDynamicSharedMemorySize, GEMM_SMEM_BYTES);
        attr_done = true;
    }

    convert_weights<<<(DIMX * 2 * DEMBX + 255) / 256, 256>>>(Wq, Wkv, Wo);
    ln_kernel<<<MROWS, 256>>>(src, ltn, gs, bs, gl, bl);
    gemm_kernel<0><<<dim3(512 / 128, 512 / 128), 256, GEMM_SMEM_BYTES>>>(nullptr);     // Q
    gemm_kernel<1><<<dim3(1024 / 128, MROWS / 128), 256, GEMM_SMEM_BYTES>>>(nullptr);  // KV
    attn_kernel<<<NSPLIT * 64, 128>>>();
    combine_kernel<<<64, 128>>>();
    gemm_kernel<2><<<dim3(768 / 128, 512 / 128), 256, GEMM_SMEM_BYTES>>>(out);         // out proj
}

// round 9
// speedup vs baseline: 1.1167x; 1.1158x over previous
#include <cuda_runtime.h>
#include <cuda_fp16.h>
#include <cstdint>

#define DIMX 768
#define DEMBX 512
#define NSRC 8192
#define NLTN 64
#define NSLAB 8
#define NCTX 8256                 // per-slab context rows (src + ltn)
#define MROWS (NSLAB * NCTX)      // 66048
#define NSPLIT 3
#define TILES_PER_SPLIT 43        // 129 tiles / 3

// ---------------- scratch (static device globals: allowed) ----------------
__device__ __half g_ctx[(size_t)MROWS * DIMX];        // normalized context, fp16
__device__ __half g_ltnc[(size_t)NSLAB * NLTN * DIMX];// compact normalized ltn
__device__ __half g_wq[DIMX * DEMBX];
__device__ __half g_wkv[DIMX * 2 * DEMBX];
__device__ __half g_wo[DEMBX * DIMX];
__device__ __half g_q[NSLAB * NLTN * DEMBX];
__device__ __half g_kv[(size_t)MROWS * 2 * DEMBX];    // K | V
__device__ __half g_att[NSLAB * NLTN * DEMBX];
__device__ float g_po[NSPLIT * 64 * 64 * 64];
__device__ float g_pm[NSPLIT * 64 * 64];
__device__ float g_pl[NSPLIT * 64 * 64];

// ---------------- helpers ----------------
__device__ __forceinline__ uint32_t smem_u32(const void* p) {
    return (uint32_t)__cvta_generic_to_shared(p);
}
__device__ __forceinline__ void cp16(uint32_t s, const void* g) {
    asm volatile("cp.async.cg.shared.global [%0], [%1], 16;\n" :: "r"(s), "l"(g));
}
#define CP_COMMIT() asm volatile("cp.async.commit_group;\n")
#define CP_WAIT0()  asm volatile("cp.async.wait_group 0;\n")
#define CP_WAIT1()  asm volatile("cp.async.wait_group 1;\n")
#define CP_WAIT2()  asm volatile("cp.async.wait_group 2;\n")

__device__ __forceinline__ void ldm_x4(uint32_t r[4], uint32_t addr) {
    asm volatile("ldmatrix.sync.aligned.m8n8.x4.shared.b16 {%0,%1,%2,%3}, [%4];\n"
        : "=r"(r[0]), "=r"(r[1]), "=r"(r[2]), "=r"(r[3]) : "r"(addr));
}
__device__ __forceinline__ void ldm_x4_t(uint32_t r[4], uint32_t addr) {
    asm volatile("ldmatrix.sync.aligned.m8n8.x4.trans.shared.b16 {%0,%1,%2,%3}, [%4];\n"
        : "=r"(r[0]), "=r"(r[1]), "=r"(r[2]), "=r"(r[3]) : "r"(addr));
}
__device__ __forceinline__ uint32_t packf(float a, float b) {
    __half2 h = __floats2half2_rn(a, b);
    return *(uint32_t*)&h;
}
__device__ __forceinline__ void mma16816(float c[4], const uint32_t a[4], const uint32_t b0, const uint32_t b1) {
    asm volatile(
        "mma.sync.aligned.m16n8k16.row.col.f32.f16.f16.f32 "
        "{%0,%1,%2,%3},{%4,%5,%6,%7},{%8,%9},{%0,%1,%2,%3};\n"
        : "+f"(c[0]), "+f"(c[1]), "+f"(c[2]), "+f"(c[3])
        : "r"(a[0]), "r"(a[1]), "r"(a[2]), "r"(a[3]), "r"(b0), "r"(b1));
}

// ---------------- weight fp32 -> fp16 ----------------
__global__ void convert_weights(const float* __restrict__ Wq,
                                const float* __restrict__ Wkv,
                                const float* __restrict__ Wo) {
    int i = blockIdx.x * blockDim.x + threadIdx.x;
    if (i < DIMX * DEMBX)     g_wq[i]  = __float2half(Wq[i]);
    if (i < DIMX * 2 * DEMBX) g_wkv[i] = __float2half(Wkv[i]);
    if (i < DEMBX * DIMX)     g_wo[i]  = __float2half(Wo[i]);
}

// ---------------- fused layernorm (src + ltn) ----------------
__global__ void __launch_bounds__(256) ln_kernel(
    const float* __restrict__ src, const float* __restrict__ ltn,
    const float* __restrict__ gs, const float* __restrict__ bs,
    const float* __restrict__ gl, const float* __restrict__ bl) {
    int row = blockIdx.x;              // 0..66047
    int slab = row / NCTX;
    int r = row - slab * NCTX;
    bool is_ltn = (r >= NSRC);
    const float* x; const float* g; const float* b;
    if (!is_ltn) { x = src + (size_t)(slab * NSRC + r) * DIMX; g = gs; b = bs; }
    else         { x = ltn + (size_t)(slab * NLTN + (r - NSRC)) * DIMX; g = gl; b = bl; }

    int t = threadIdx.x;
    float v0 = x[t], v1 = x[t + 256], v2 = x[t + 512];
    float s = v0 + v1 + v2;
    float s2 = v0 * v0 + v1 * v1 + v2 * v2;
    #pragma unroll
    for (int o = 16; o; o >>= 1) {
        s  += __shfl_xor_sync(0xffffffffu, s, o);
        s2 += __shfl_xor_sync(0xffffffffu, s2, o);
    }
    __shared__ float ss[8], ss2[8];
    int w = t >> 5, l = t & 31;
    if (l == 0) { ss[w] = s; ss2[w] = s2; }
    __syncthreads();
    __shared__ float mv[2];
    if (t == 0) {
        float a = 0.f, a2 = 0.f;
        #pragma unroll
        for (int i = 0; i < 8; i++) { a += ss[i]; a2 += ss2[i]; }
        float mean = a * (1.f / 768.f);
        float var  = a2 * (1.f / 768.f) - mean * mean;
        mv[0] = mean;
        mv[1] = rsqrtf(var + 1e-5f);
    }
    __syncthreads();
    float mean = mv[0], rstd = mv[1];

    __half* out = g_ctx + (size_t)row * DIMX;
    __half* out2 = is_ltn ? (g_ltnc + (size_t)(slab * NLTN + (r - NSRC)) * DIMX) : nullptr;
    float vv[3] = {v0, v1, v2};
    #pragma unroll
    for (int i = 0; i < 3; i++) {
        int c = t + i * 256;
        float y = (vv[i] - mean) * rstd * g[c] + b[c];
        __half h = __float2half(y);
        out[c] = h;
        if (out2) out2[c] = h;
    }
}

// ---------------- fp16 MMA GEMM: warp tile 64x64, 4 warps, 4-stage ring ----------------
// BM=128, BN=128, BK=32, 128 thr. Warp w: rows (w>>1)*64, cols (w&1)*64.
// MODE 0: g_q   = g_ltnc @ g_wq   (512  x 512 , K=768)  -> half
// MODE 1: g_kv  = g_ctx  @ g_wkv  (66048x 1024, K=768)  -> half
// MODE 2: dout  = g_att  @ g_wo   (512  x 768 , K=512)  -> float
#define GSTG 4
#define A_HALVES (128 * 40)
#define B_HALVES (32 * 136)
#define STG_HALVES (A_HALVES + B_HALVES)        // 9472
#define GEMM_SMEM_BYTES (GSTG * STG_HALVES * 2) // 75776

template <int MODE>
__global__ void __launch_bounds__(128, 2) gemm_kernel(float* __restrict__ dout) {
    constexpr int N = (MODE == 0) ? 512 : ((MODE == 1) ? 1024 : 768);
    constexpr int K = (MODE == 2) ? 512 : 768;
    const __half* A = (MODE == 0) ? g_ltnc : ((MODE == 1) ? g_ctx : g_att);
    const __half* B = (MODE == 0) ? g_wq  : ((MODE == 1) ? g_wkv : g_wo);
    __half* Ch      = (MODE == 0) ? g_q   : g_kv;

    extern __shared__ __half dyn[];

    const int m0 = blockIdx.y * 128, n0 = blockIdx.x * 128;
    const int tid = threadIdx.x;
    const int warp = tid >> 5, lane = tid & 31;
    const int wm = (warp >> 1) * 64, wn = (warp & 1) * 64;
    const int r = lane >> 2, q = lane & 3;
    const int rr = lane & 7, tt = lane >> 3;   // ldmatrix lane decomposition

    float acc[4][8][4];
    #pragma unroll
    for (int i = 0; i < 4; i++)
        #pragma unroll
        for (int j = 0; j < 8; j++)
            #pragma unroll
            for (int k = 0; k < 4; k++) acc[i][j][k] = 0.f;

    // loader offsets: 128 threads, 4 cp16 for A (128x32) + 4 for B (32x128)
    const int a_row = tid >> 2, a_col = (tid & 3) * 8;    // rows 0..31 (+32 steps)
    const int b_row = tid >> 4, b_col = (tid & 15) * 8;   // rows 0..7  (+8 steps)

    auto load_stage = [&](int s, int k0) {
        __half* As = dyn + s * STG_HALVES;
        __half* Bs = As + A_HALVES;
        #pragma unroll
        for (int i = 0; i < 4; i++) {
            int row = a_row + i * 32;
            cp16(smem_u32(&As[row * 40 + a_col]),
                 A + (size_t)(m0 + row) * K + k0 + a_col);
        }
        #pragma unroll
        for (int i = 0; i < 4; i++) {
            int row = b_row + i * 8;
            cp16(smem_u32(&Bs[row * 136 + b_col]),
                 B + (size_t)(k0 + row) * N + n0 + b_col);
        }
    };

    constexpr int NIT = K / 32;
    load_stage(0, 0);  CP_COMMIT();
    load_stage(1, 32); CP_COMMIT();
    load_stage(2, 64); CP_COMMIT();

    for (int it = 0; it < NIT; ++it) {
        if (it + 2 < NIT)      { CP_WAIT2(); }
        else if (it + 1 < NIT) { CP_WAIT1(); }
        else                   { CP_WAIT0(); }
        __syncthreads();

        if (it + 3 < NIT) { load_stage((it + 3) & (GSTG - 1), (it + 3) * 32); CP_COMMIT(); }

        const int s = it & (GSTG - 1);
        __half* As = dyn + s * STG_HALVES;
        __half* Bs = As + A_HALVES;

        // A fragments: 4 m-tiles x 2 k-tiles
        uint32_t af[4][2][4];
        #pragma unroll
        for (int mt = 0; mt < 4; mt++)
            #pragma unroll
            for (int kt = 0; kt < 2; kt++) {
                int row = wm + 16 * mt + (tt & 1) * 8 + rr;
                int col = kt * 16 + (tt >> 1) * 8;
                ldm_x4(af[mt][kt], smem_u32(&As[row * 40 + col]));
            }
        // B fragments + MMAs
        #pragma unroll
        for (int kt = 0; kt < 2; kt++) {
            uint32_t bf[4][4];
            #pragma unroll
            for (int np = 0; np < 4; np++) {
                int krow = kt * 16 + (tt & 1) * 8 + rr;
                int col  = wn + np * 16 + (tt >> 1) * 8;
                ldm_x4_t(bf[np], smem_u32(&Bs[krow * 136 + col]));
            }
            #pragma unroll
            for (int np = 0; np < 4; np++)
                #pragma unroll
                for (int mt = 0; mt < 4; mt++) {
                    mma16816(acc[mt][2 * np],     af[mt][kt], bf[np][0], bf[np][1]);
                    mma16816(acc[mt][2 * np + 1], af[mt][kt], bf[np][2], bf[np][3]);
                }
        }
    }

    #pragma unroll
    for (int mt = 0; mt < 4; mt++)
        #pragma unroll
        for (int nt = 0; nt < 8; nt++) {
            int row = m0 + wm + 16 * mt + r;
            int col = n0 + wn + nt * 8 + q * 2;
            if (MODE == 2) {
                *(float2*)&dout[(size_t)row * N + col] =
                    make_float2(acc[mt][nt][0], acc[mt][nt][1]);
                *(float2*)&dout[(size_t)(row + 8) * N + col] =
                    make_float2(acc[mt][nt][2], acc[mt][nt][3]);
            } else {
                *(__half2*)&Ch[(size_t)row * N + col] =
                    __floats2half2_rn(acc[mt][nt][0], acc[mt][nt][1]);
                *(__half2*)&Ch[(size_t)(row + 8) * N + col] =
                    __floats2half2_rn(acc[mt][nt][2], acc[mt][nt][3]);
            }
        }
}

// ---------------- split-context flash attention ----------------
__global__ void __launch_bounds__(128) attn_kernel() {
    const int split = blockIdx.x >> 6;
    const int sh = blockIdx.x & 63;
    const int slab = sh >> 3, h = sh & 7;
    __shared__ __half Qs[64][72];
    __shared__ __half Ks[2][64][72];
    __shared__ __half Vs[2][64][72];
    const int tid = threadIdx.x, warp = tid >> 5, lane = tid & 31;
    const int r = lane >> 2, q = lane & 3;
    const int rr = lane & 7, tt = lane >> 3;

    for (int i = tid; i < 512; i += 128) {
        int row = i >> 3, c = (i & 7) * 8;
        *(uint4*)&Qs[row][c] =
            *(const uint4*)&g_q[(size_t)(slab * 64 + row) * DEMBX + h * 64 + c];
    }
    __syncthreads();

    uint32_t qa[4][4];
    #pragma unroll
    for (int kt = 0; kt < 4; kt++) {
        int row = warp * 16 + (tt & 1) * 8 + rr;
        int col = kt * 16 + (tt >> 1) * 8;
        ldm_x4(qa[kt], smem_u32(&Qs[row][col]));
    }

    float o[8][4];
    #pragma unroll
    for (int nt = 0; nt < 8; nt++)
        #pragma unroll
        for (int i = 0; i < 4; i++) o[nt][i] = 0.f;
    float m0 = -1e30f, m1 = -1e30f, l0 = 0.f, l1 = 0.f;

    const size_t rowbase = (size_t)slab * NCTX + (size_t)split * TILES_PER_SPLIT * 64;
    auto load_kv = [&](int s, int c0) {
        #pragma unroll
        for (int i = 0; i < 4; i++) {
            int id = tid + i * 128;
            int row = id >> 3, cc = (id & 7) * 8;
            const __half* srcp = g_kv + (rowbase + c0 + row) * 1024 + h * 64 + cc;
            cp16(smem_u32(&Ks[s][row][cc]), srcp);
            cp16(smem_u32(&Vs[s][row][cc]), srcp + 512);
        }
    };

    load_kv(0, 0);
    CP_COMMIT();
    const int NIT = TILES_PER_SPLIT;
    for (int it = 0; it < NIT; ++it) {
        CP_WAIT0();
        __syncthreads();
        if (it + 1 < NIT) { load_kv((it + 1) & 1, (it + 1) * 64); CP_COMMIT(); }
        int s = it & 1;

        float sf[8][4];
        #pragma unroll
        for (int nt = 0; nt < 8; nt++)
            #pragma unroll
            for (int i = 0; i < 4; i++) sf[nt][i] = 0.f;
        #pragma unroll
        for (int kt = 0; kt < 4; kt++) {
            uint32_t kb[4][4];
            #pragma unroll
            for (int np = 0; np < 4; np++) {
                int nrow = np * 16 + (tt >> 1) * 8 + rr;
                int col  = kt * 16 + (tt & 1) * 8;
                ldm_x4(kb[np], smem_u32(&Ks[s][nrow][col]));
            }
            #pragma unroll
            for (int np = 0; np < 4; np++) {
                mma16816(sf[2 * np],     qa[kt], kb[np][0], kb[np][1]);
                mma16816(sf[2 * np + 1], qa[kt], kb[np][2], kb[np][3]);
            }
        }
        float mn0 = m0, mn1 = m1;
        #pragma unroll
        for (int nt = 0; nt < 8; nt++) {
            sf[nt][0] *= 0.125f; sf[nt][1] *= 0.125f;
            sf[nt][2] *= 0.125f; sf[nt][3] *= 0.125f;
            mn0 = fmaxf(mn0, fmaxf(sf[nt][0], sf[nt][1]));
            mn1 = fmaxf(mn1, fmaxf(sf[nt][2], sf[nt][3]));
        }
        mn0 = fmaxf(mn0, __shfl_xor_sync(0xffffffffu, mn0, 1));
        mn0 = fmaxf(mn0, __shfl_xor_sync(0xffffffffu, mn0, 2));
        mn1 = fmaxf(mn1, __shfl_xor_sync(0xffffffffu, mn1, 1));
        mn1 = fmaxf(mn1, __shfl_xor_sync(0xffffffffu, mn1, 2));
        float a0 = __expf(m0 - mn0), a1 = __expf(m1 - mn1);
        float rs0 = 0.f, rs1 = 0.f;
        #pragma unroll
        for (int nt = 0; nt < 8; nt++) {
            sf[nt][0] = __expf(sf[nt][0] - mn0);
            sf[nt][1] = __expf(sf[nt][1] - mn0);
            sf[nt][2] = __expf(sf[nt][2] - mn1);
            sf[nt][3] = __expf(sf[nt][3] - mn1);
            rs0 += sf[nt][0] + sf[nt][1];
            rs1 += sf[nt][2] + sf[nt][3];
        }
        rs0 += __shfl_xor_sync(0xffffffffu, rs0, 1);
        rs0 += __shfl_xor_sync(0xffffffffu, rs0, 2);
        rs1 += __shfl_xor_sync(0xffffffffu, rs1, 1);
        rs1 += __shfl_xor_sync(0xffffffffu, rs1, 2);
        l0 = l0 * a0 + rs0; l1 = l1 * a1 + rs1;
        m0 = mn0; m1 = mn1;
        #pragma unroll
        for (int nt = 0; nt < 8; nt++) {
            o[nt][0] *= a0; o[nt][1] *= a0;
            o[nt][2] *= a1; o[nt][3] *= a1;
        }
        uint32_t pa[4][4];
        #pragma unroll
        for (int t2 = 0; t2 < 4; t2++) {
            pa[t2][0] = packf(sf[2 * t2][0],     sf[2 * t2][1]);
            pa[t2][1] = packf(sf[2 * t2][2],     sf[2 * t2][3]);
            pa[t2][2] = packf(sf[2 * t2 + 1][0], sf[2 * t2 + 1][1]);
            pa[t2][3] = packf(sf[2 * t2 + 1][2], sf[2 * t2 + 1][3]);
        }
        #pragma unroll
        for (int kt = 0; kt < 4; kt++) {
            uint32_t vb[4][4];
            #pragma unroll
            for (int np = 0; np < 4; np++) {
                int krow = kt * 16 + (tt & 1) * 8 + rr;
                int col  = np * 16 + (tt >> 1) * 8;
                ldm_x4_t(vb[np], smem_u32(&Vs[s][krow][col]));
            }
            #pragma unroll
            for (int np = 0; np < 4; np++) {
                mma16816(o[2 * np],     pa[kt], vb[np][0], vb[np][1]);
                mma16816(o[2 * np + 1], pa[kt], vb[np][2], vb[np][3]);
            }
        }
    }

    float* po = g_po + (size_t)blockIdx.x * 4096;
    #pragma unroll
    for (int nt = 0; nt < 8; nt++) {
        int row = warp * 16 + r;
        int col = nt * 8 + q * 2;
        *(float2*)&po[row * 64 + col]       = make_float2(o[nt][0], o[nt][1]);
        *(float2*)&po[(row + 8) * 64 + col] = make_float2(o[nt][2], o[nt][3]);
    }
    if (q == 0) {
        int row = warp * 16 + r;
        g_pm[blockIdx.x * 64 + row]     = m0;
        g_pm[blockIdx.x * 64 + row + 8] = m1;
        g_pl[blockIdx.x * 64 + row]     = l0;
        g_pl[blockIdx.x * 64 + row + 8] = l1;
    }
}

// ---------------- combine split partials -> g_att (fp16) ----------------
__global__ void __launch_bounds__(128) combine_kernel() {
    const int sh = blockIdx.x;
    const int slab = sh >> 3, h = sh & 7;
    __shared__ float wsh[NSPLIT][64];
    __shared__ float invl[64];
    int tid = threadIdx.x;
    if (tid < 64) {
        float m[NSPLIT], l[NSPLIT];
        float M = -1e30f;
        #pragma unroll
        for (int s = 0; s < NSPLIT; s++) {
            m[s] = g_pm[(s * 64 + sh) * 64 + tid];
            l[s] = g_pl[(s * 64 + sh) * 64 + tid];
            M = fmaxf(M, m[s]);
        }
        float L = 0.f;
        #pragma unroll
        for (int s = 0; s < NSPLIT; s++) {
            float w = __expf(m[s] - M);
            wsh[s][tid] = w;
            L += w * l[s];
        }
        invl[tid] = 1.f / L;
    }
    __syncthreads();
    for (int i = tid; i < 4096; i += 128) {
        int row = i >> 6, col = i & 63;
        float acc = 0.f;
        #pragma unroll
        for (int s = 0; s < NSPLIT; s++)
            acc += wsh[s][row] * g_po[(size_t)(s * 64 + sh) * 4096 + i];
        g_att[(size_t)(slab * 64 + row) * DEMBX + h * 64 + col] =
            __float2half(acc * invl[row]);
    }
}

// ---------------- launch ----------------
extern "C" void kernel_launch(void* const* d_in, const int* in_sizes, int n_in,
                              void* d_out, int out_size) {
    const float* src  = (const float*)d_in[0];
    const float* ltn  = (const float*)d_in[1];
    const float* gs   = (const float*)d_in[2];
    const float* bs   = (const float*)d_in[3];
    const float* gl   = (const float*)d_in[4];
    const float* bl   = (const float*)d_in[5];
    const float* Wq   = (const float*)d_in[6];
    const float* Wkv  = (const float*)d_in[7];
    const float* Wo   = (const float*)d_in[8];
    float* out = (float*)d_out;

    static bool attr_done = false;
    if (!attr_done) {
        cudaFuncSetAttribute(gemm_kernel<0>, cudaFuncAttributeMaxDynamicSharedMemorySize, GEMM_SMEM_BYTES);
        cudaFuncSetAttribute(gemm_kernel<1>, cudaFuncAttributeMaxDynamicSharedMemorySize, GEMM_SMEM_BYTES);
        cudaFuncSetAttribute(gemm_kernel<2>, cudaFuncAttributeMaxDynamicSharedMemorySize, GEMM_SMEM_BYTES);
        attr_done = true;
    }

    convert_weights<<<(DIMX * 2 * DEMBX + 255) / 256, 256>>>(Wq, Wkv, Wo);
    ln_kernel<<<MROWS, 256>>>(src, ltn, gs, bs, gl, bl);
    gemm_kernel<0><<<dim3(512 / 128, 512 / 128), 128, GEMM_SMEM_BYTES>>>(nullptr);     // Q
    gemm_kernel<1><<<dim3(1024 / 128, MROWS / 128), 128, GEMM_SMEM_BYTES>>>(nullptr);  // KV
    attn_kernel<<<NSPLIT * 64, 128>>>();
    combine_kernel<<<64, 128>>>();
    gemm_kernel<2><<<dim3(768 / 128, 512 / 128), 128, GEMM_SMEM_BYTES>>>(out);         // out proj
}